// round 8
// baseline (speedup 1.0000x reference)
#include <cuda_runtime.h>

#define HH 768
#define WW 768
#define CC 64
#define NSEG 385
#define NTHREADS 256
#define PER_T (HH / 64)          // mask elems per scan thread (first 64 threads)
#define GRID_BLOCKS (148 * 8)

// ---------------------------------------------------------------------------
// Fully fused grid pooling, 256-thread blocks:
//   thread layout: xo = t&3 (x offset), cg = (t>>2)&15 (channel quad),
//                  yo = t>>6 (y offset 0..3).
//   Average cell (~4x4 px) = 256 float4 = exactly one load per thread,
//   entire rectangle in flight at once.
//   Reduce: xor-shfl over xo (in-warp) -> smem exchange over yo (1 barrier,
//   double-buffered) -> every thread holds the mean -> rectangle broadcast
//   at 16 px/iteration.
//   Traffic floor: 151MB read + 151MB write.
// ---------------------------------------------------------------------------
__global__ void __launch_bounds__(NTHREADS)
fused_grid_pool(const float* __restrict__ in,
                const int* __restrict__ h_mask,
                const int* __restrict__ v_mask,
                float* __restrict__ out) {
    __shared__ int    s_row_start[NSEG + 1];
    __shared__ int    s_col_start[NSEG + 1];
    __shared__ int    s_tmp[2];
    __shared__ int    s_nrow, s_ncol;
    __shared__ float4 s_part[2][4][16];   // [buf][yo][cg]

    const int t = threadIdx.x;

    // ---- prolog: first 64 threads build segment starts for both masks ----
    #pragma unroll
    for (int axis = 0; axis < 2; ++axis) {
        const int* m = (axis == 0) ? h_mask : v_mask;
        int* start   = (axis == 0) ? s_row_start : s_col_start;

        int v = 0, rises = 0, cnt = 0, excl_base = 0;
        if (t < 64) {
            const int lane = t & 31, w = t >> 5;
            const int base = t * PER_T;
            int pm = (base == 0) ? 1 : m[base - 1];
            #pragma unroll
            for (int k = 0; k < PER_T; ++k) {
                const int mv = m[base + k];
                const int r = (mv == 1 && pm == 0);
                rises |= (r << k);
                cnt += r;
                pm = mv;
            }
            v = cnt;
            #pragma unroll
            for (int o = 1; o < 32; o <<= 1) {
                int n = __shfl_up_sync(0xFFFFFFFFu, v, o);
                if (lane >= o) v += n;
            }
            if (lane == 31) s_tmp[w] = v;
        }
        __syncthreads();
        if (t < 64) {
            const int w = t >> 5;
            const int add   = (w == 1) ? s_tmp[0] : 0;
            const int total = s_tmp[0] + s_tmp[1];
            excl_base = v + add - cnt;

            int sid = excl_base;
            #pragma unroll
            for (int k = 0; k < PER_T; ++k) {
                if ((rises >> k) & 1) { ++sid; start[sid] = t * PER_T + k; }
            }
            const int nseg = total + 1;
            if (t == 0) {
                start[0] = 0; start[nseg] = HH;
                if (axis == 0) s_nrow = nseg; else s_ncol = nseg;
            }
        }
        __syncthreads();
    }

    const int nrow = s_nrow, ncol = s_ncol;
    const int total_cells = nrow * ncol;

    const int xo = t & 3;
    const int cg = (t >> 2) & 15;
    const int yo = t >> 6;

    int buf = 0;

    for (int cell = blockIdx.x; cell < total_cells; cell += GRID_BLOCKS) {
        const int rseg = cell / ncol;
        const int cseg = cell - rseg * ncol;
        const int cs = s_col_start[cseg], ce = s_col_start[cseg + 1];
        const int rs = s_row_start[rseg], re = s_row_start[rseg + 1];

        // ---- rectangle sum: threads tile 4x4 px x 16 quads per sweep ----
        float4 acc = make_float4(0.f, 0.f, 0.f, 0.f);
        for (int y = rs + yo; y < re; y += 4) {
            const float4* rowp = reinterpret_cast<const float4*>(
                in + (size_t)y * WW * CC);
            for (int x = cs + xo; x < ce; x += 4) {
                const float4 v = __ldg(&rowp[x * 16 + cg]);
                acc.x += v.x; acc.y += v.y; acc.z += v.z; acc.w += v.w;
            }
        }

        // in-warp reduce across the 4 xo lanes (lane = xo + 4*(cg&7))
        #pragma unroll
        for (int o = 1; o < 4; o <<= 1) {
            acc.x += __shfl_xor_sync(0xFFFFFFFFu, acc.x, o);
            acc.y += __shfl_xor_sync(0xFFFFFFFFu, acc.y, o);
            acc.z += __shfl_xor_sync(0xFFFFFFFFu, acc.z, o);
            acc.w += __shfl_xor_sync(0xFFFFFFFFu, acc.w, o);
        }
        if (xo == 0) s_part[buf][yo][cg] = acc;
        __syncthreads();

        // cross-yo reduce: 4 broadcast LDS per thread, everyone gets the mean
        const float4 p0 = s_part[buf][0][cg];
        const float4 p1 = s_part[buf][1][cg];
        const float4 p2 = s_part[buf][2][cg];
        const float4 p3 = s_part[buf][3][cg];
        const float inv = 1.0f / (float)((re - rs) * (ce - cs));
        float4 mv;
        mv.x = (p0.x + p1.x + p2.x + p3.x) * inv;
        mv.y = (p0.y + p1.y + p2.y + p3.y) * inv;
        mv.z = (p0.z + p1.z + p2.z + p3.z) * inv;
        mv.w = (p0.w + p1.w + p2.w + p3.w) * inv;

        // ---- broadcast: 16 px per sweep ----
        for (int y = rs + yo; y < re; y += 4) {
            float4* ro = reinterpret_cast<float4*>(out + (size_t)y * WW * CC);
            for (int x = cs + xo; x < ce; x += 4)
                ro[x * 16 + cg] = mv;
        }

        buf ^= 1;   // WAR-safe without a second barrier
    }
}

// ---------------------------------------------------------------------------
extern "C" void kernel_launch(void* const* d_in, const int* in_sizes, int n_in,
                              void* d_out, int out_size) {
    const float* in = (const float*)d_in[0];
    const int*   hm = (const int*)d_in[1];
    const int*   vm = (const int*)d_in[2];
    float*       out = (float*)d_out;

    fused_grid_pool<<<GRID_BLOCKS, NTHREADS>>>(in, hm, vm, out);
}

// round 9
// speedup vs baseline: 2.0000x; 2.0000x over previous
#include <cuda_runtime.h>

#define HH 768
#define WW 768
#define CC 64
#define NSEG 385
#define NTHREADS 64
#define PER_T (HH / NTHREADS)     // 12 mask elems per scan thread
#define GRID_BLOCKS 4736          // 148 SM x 32 CTA slots (finer tail balancing)
#define NWARPS_TOTAL (GRID_BLOCKS * 2)

// ---------------------------------------------------------------------------
// Fused grid pooling, WARP-per-cell:
//   prolog: every block redundantly scans both masks into SMEM segment tables
//           (L2-broadcast loads + 64-thread scan; no inter-kernel deps).
//   main:   each 32-lane warp owns one cell at a time (grid-stride over
//           compact cell ids). Lane layout: cg = lane&15 (channel quad),
//           xo = lane>>4 (x parity). A warp access = 2 whole pixels = 512B
//           fully coalesced. Reduce = ONE shfl_xor(16) stage. No barriers,
//           no smem traffic in the main loop.
//   Traffic floor: 151MB read + 151MB write.
// ---------------------------------------------------------------------------
__global__ void __launch_bounds__(NTHREADS, 28)
fused_grid_pool(const float* __restrict__ in,
                const int* __restrict__ h_mask,
                const int* __restrict__ v_mask,
                float* __restrict__ out) {
    __shared__ int s_row_start[NSEG + 1];
    __shared__ int s_col_start[NSEG + 1];
    __shared__ int s_tmp[2];
    __shared__ int s_nrow, s_ncol;

    const int t = threadIdx.x;
    const int lane = t & 31, w = t >> 5;

    // ---- prolog: build segment starts for both masks (identical to R6) ----
    #pragma unroll
    for (int axis = 0; axis < 2; ++axis) {
        const int* m = (axis == 0) ? h_mask : v_mask;
        int* start   = (axis == 0) ? s_row_start : s_col_start;

        const int base = t * PER_T;
        int pm = (base == 0) ? 1 : m[base - 1];   // pm=1 at i=0 forces rise[0]=0
        int rises = 0, cnt = 0;
        #pragma unroll
        for (int k = 0; k < PER_T; ++k) {
            const int mv = m[base + k];
            const int r = (mv == 1 && pm == 0);
            rises |= (r << k);
            cnt += r;
            pm = mv;
        }
        int v = cnt;
        #pragma unroll
        for (int o = 1; o < 32; o <<= 1) {
            int n = __shfl_up_sync(0xFFFFFFFFu, v, o);
            if (lane >= o) v += n;
        }
        if (lane == 31) s_tmp[w] = v;
        __syncthreads();
        const int add   = (w == 1) ? s_tmp[0] : 0;
        const int total = s_tmp[0] + s_tmp[1];
        const int excl  = v + add - cnt;

        int sid = excl;
        #pragma unroll
        for (int k = 0; k < PER_T; ++k) {
            if ((rises >> k) & 1) { ++sid; start[sid] = base + k; }
        }
        const int nseg = total + 1;
        if (t == 0) {
            start[0] = 0; start[nseg] = HH;
            if (axis == 0) s_nrow = nseg; else s_ncol = nseg;
        }
        __syncthreads();
    }

    const int nrow = s_nrow, ncol = s_ncol;
    const int total_cells = nrow * ncol;

    const int cg = lane & 15;     // channel quad 0..15  (low bits -> 256B runs)
    const int xo = lane >> 4;     // x parity 0/1

    // ---- main: warp-per-cell grid-stride, zero barriers ----
    for (int cell = blockIdx.x * 2 + w; cell < total_cells; cell += NWARPS_TOTAL) {
        const int rseg = cell / ncol;
        const int cseg = cell - rseg * ncol;
        const int cs = s_col_start[cseg], ce = s_col_start[cseg + 1];
        const int rs = s_row_start[rseg], re = s_row_start[rseg + 1];

        float4 a0 = make_float4(0.f, 0.f, 0.f, 0.f);
        float4 a1 = make_float4(0.f, 0.f, 0.f, 0.f);

        int y = rs;
        for (; y + 1 < re; y += 2) {
            const float4* r0 = reinterpret_cast<const float4*>(
                in + (size_t)y * WW * CC);
            const float4* r1 = r0 + WW * (CC / 4);
            #pragma unroll 2
            for (int x = cs + xo; x < ce; x += 2) {
                const float4 v0 = __ldg(&r0[x * 16 + cg]);
                const float4 v1 = __ldg(&r1[x * 16 + cg]);
                a0.x += v0.x; a0.y += v0.y; a0.z += v0.z; a0.w += v0.w;
                a1.x += v1.x; a1.y += v1.y; a1.z += v1.z; a1.w += v1.w;
            }
        }
        if (y < re) {
            const float4* r0 = reinterpret_cast<const float4*>(
                in + (size_t)y * WW * CC);
            #pragma unroll 2
            for (int x = cs + xo; x < ce; x += 2) {
                const float4 v0 = __ldg(&r0[x * 16 + cg]);
                a0.x += v0.x; a0.y += v0.y; a0.z += v0.z; a0.w += v0.w;
            }
        }
        a0.x += a1.x; a0.y += a1.y; a0.z += a1.z; a0.w += a1.w;

        // single-stage reduce across the two x parities (lanes +-16)
        a0.x += __shfl_xor_sync(0xFFFFFFFFu, a0.x, 16);
        a0.y += __shfl_xor_sync(0xFFFFFFFFu, a0.y, 16);
        a0.z += __shfl_xor_sync(0xFFFFFFFFu, a0.z, 16);
        a0.w += __shfl_xor_sync(0xFFFFFFFFu, a0.w, 16);

        const float inv = 1.0f / (float)((re - rs) * (ce - cs));
        const float4 mv = make_float4(a0.x * inv, a0.y * inv,
                                      a0.z * inv, a0.w * inv);

        // broadcast: warp writes 2 whole pixels (512B) per sweep
        for (int y2 = rs; y2 < re; ++y2) {
            float4* ro = reinterpret_cast<float4*>(out + (size_t)y2 * WW * CC);
            for (int x = cs + xo; x < ce; x += 2)
                ro[x * 16 + cg] = mv;
        }
    }
}

// ---------------------------------------------------------------------------
extern "C" void kernel_launch(void* const* d_in, const int* in_sizes, int n_in,
                              void* d_out, int out_size) {
    const float* in = (const float*)d_in[0];
    const int*   hm = (const int*)d_in[1];
    const int*   vm = (const int*)d_in[2];
    float*       out = (float*)d_out;

    fused_grid_pool<<<GRID_BLOCKS, NTHREADS>>>(in, hm, vm, out);
}